// round 12
// baseline (speedup 1.0000x reference)
#include <cuda_runtime.h>
#include <cuda_fp16.h>
#include <cstdint>

// ---------------------------------------------------------------------------
// WaveletAttention: 3-level MODWT (db4 dilated circular convs) -> MHA
// B=4, L=2048, D=512, H=8, dh=64
// Round 12: fully-fused 2-kernel MODWT cascade (smem-tiled, no intermediate
//           round-trips) + round-11 2-MMA scaled-residual attention (exp2)
// ---------------------------------------------------------------------------

#define Bn  4
#define Ln  2048
#define Dn  512
#define Hn  8
#define NBD (Bn * Ln * Dn)   // 4,194,304

#define LAM 32.0f
#define C1  0.96875f    // 1 - 1/32
#define C2  0.03125f    // 1/32

__device__ float  g_v1 [NBD];   // level-1 lowpass (only stored intermediate)
__device__ float  g_q  [NBD];
__device__ __half g_kh [NBD];   // K hi, [B][L][D]
__device__ __half g_kx [NBD];   // K X-form
__device__ __half g_vth[NBD];   // V^T hi, [B*H][64][L]
__device__ __half g_vtx[NBD];   // V^T X-form

// ---------------------------------------------------------------------------
__device__ __forceinline__ void split_x2(float x, float y,
                                         unsigned& hi, unsigned& xx) {
    __half hx = __float2half_rn(x);
    __half hy = __float2half_rn(y);
    float fx = __half2float(hx), fy = __half2float(hy);
    __half xxh = __float2half_rn(fx + LAM * (x - fx));
    __half xyh = __float2half_rn(fy + LAM * (y - fy));
    hi = ((unsigned)__half_as_ushort(hy) << 16) | __half_as_ushort(hx);
    xx = ((unsigned)__half_as_ushort(xyh) << 16) | __half_as_ushort(xxh);
}
__device__ __forceinline__ void split_x1(float x, __half& hi, __half& xx) {
    hi = __float2half_rn(x);
    float fh = __half2float(hi);
    xx = __float2half_rn(fh + LAM * (x - fh));
}

__device__ __forceinline__ void mma_f16(float* c, const unsigned* a,
                                        unsigned b0, unsigned b1) {
    asm("mma.sync.aligned.m16n8k16.row.col.f32.f16.f16.f32 "
        "{%0,%1,%2,%3}, {%4,%5,%6,%7}, {%8,%9}, {%0,%1,%2,%3};"
        : "+f"(c[0]), "+f"(c[1]), "+f"(c[2]), "+f"(c[3])
        : "r"(a[0]), "r"(a[1]), "r"(a[2]), "r"(a[3]), "r"(b0), "r"(b1));
}

__device__ __forceinline__ float ex2f(float x) {
    float r;
    asm("ex2.approx.ftz.f32 %0, %1;" : "=f"(r) : "f"(x));
    return r;
}

__device__ __forceinline__ uint32_t s2u(const void* p) {
    uint32_t a;
    asm("{ .reg .u64 t; cvta.to.shared.u64 t, %1; cvt.u32.u64 %0, t; }"
        : "=r"(a) : "l"(p));
    return a;
}

#define CP_ASYNC16(daddr, src)                                                 \
    asm volatile("cp.async.cg.shared.global [%0], [%1], 16;"                   \
                 :: "r"(daddr), "l"(src))
#define CP_COMMIT()  asm volatile("cp.async.commit_group;" ::: "memory")
#define CP_WAIT0()   asm volatile("cp.async.wait_group 0;" ::: "memory")

// ---------------------------------------------------------------------------
// K1: x -> {q = H0(L0(x)), v1 = L1(L0(x))}
// block (t-tile 128, d-chunk 32, b); v0 lives only in smem.
// x halo: 21 rows (v0 needs 7, q/v1 need 14 more of v0)
// ---------------------------------------------------------------------------
__global__ __launch_bounds__(256) void fconv1_kernel(
    const float* __restrict__ x, float* __restrict__ q, float* __restrict__ v1,
    const float* __restrict__ vf, const float* __restrict__ wf)
{
    __shared__ float sx [149 * 32];
    __shared__ float sv0[142 * 32];
    const int t0 = blockIdx.x * 128, d0 = blockIdx.y * 32, b = blockIdx.z;
    const int tid = threadIdx.x;
    const size_t LL = (size_t)Ln * Ln;

    float tL0[8], tH0[8], tL1[8];
#pragma unroll
    for (int k = 0; k < 8; k++) {
        tL0[k] = __ldg(&vf[(2048 - k) & 2047]);
        tH0[k] = __ldg(&wf[(2048 - k) & 2047]);
        tL1[k] = __ldg(&vf[LL + ((2048 - 2 * k) & 2047)]);
    }

    const float* xb = x + ((long)b << 20) + d0;
    for (int e = tid; e < 149 * 32; e += 256) {
        int r = e >> 5, d = e & 31;
        int tg = (t0 - 21 + r) & 2047;
        sx[e] = xb[((long)tg << 9) + d];
    }
    __syncthreads();

    // v0 rows r=0..141 (global t = t0-14+r): v0[t] = sum tL0[k]*x[t-k]
    for (int e = tid; e < 142 * 32; e += 256) {
        int r = e >> 5, d = e & 31;
        float a = 0.f;
#pragma unroll
        for (int k = 0; k < 8; k++) a += tL0[k] * sx[(r + 7 - k) * 32 + d];
        sv0[e] = a;
    }
    __syncthreads();

    float* qb  = q  + ((long)b << 20) + d0;
    float* v1b = v1 + ((long)b << 20) + d0;
    for (int e = tid; e < 128 * 32; e += 256) {
        int r = e >> 5, d = e & 31;
        float aq = 0.f, a1 = 0.f;
#pragma unroll
        for (int k = 0; k < 8; k++) {
            aq += tH0[k] * sv0[(r + 14 - k) * 32 + d];
            a1 += tL1[k] * sv0[(r + 14 - 2 * k) * 32 + d];
        }
        long off = ((long)(t0 + r) << 9) + d;
        qb[off]  = aq;
        v1b[off] = a1;
    }
}

// ---------------------------------------------------------------------------
// K2: v1 -> {K = H1(v1) split hi/X,  V^T = transpose(H2(L2(v1))) split hi/X}
// v2 lives only in smem. v1 halo: 56 rows.
// dyn smem: sv1[184*32]f + sv2[156*32]f + vvh[128*33]h + vvx[128*33]h = 60416 B
// ---------------------------------------------------------------------------
#define K2_SMEM (184*32*4 + 156*32*4 + 2 * 128*33*2)

__global__ __launch_bounds__(256) void fconv2_kernel(
    const float* __restrict__ v1g,
    __half* __restrict__ khg, __half* __restrict__ kxg,
    __half* __restrict__ vth, __half* __restrict__ vtx,
    const float* __restrict__ vf, const float* __restrict__ wf)
{
    extern __shared__ float smf[];
    float*  sv1 = smf;                      // 184*32
    float*  sv2 = sv1 + 184 * 32;           // 156*32
    __half* vvh = (__half*)(sv2 + 156 * 32);
    __half* vvx = vvh + 128 * 33;

    const int t0 = blockIdx.x * 128, d0 = blockIdx.y * 32, b = blockIdx.z;
    const int tid = threadIdx.x;
    const size_t LL = (size_t)Ln * Ln;

    float tH1[8], tL2[8], tH2[8];
#pragma unroll
    for (int k = 0; k < 8; k++) {
        tH1[k] = __ldg(&wf[LL + ((2048 - 2 * k) & 2047)]);
        tL2[k] = __ldg(&vf[2 * LL + ((2048 - 4 * k) & 2047)]);
        tH2[k] = __ldg(&wf[2 * LL + ((2048 - 4 * k) & 2047)]);
    }

    const float* vb = v1g + ((long)b << 20) + d0;
    for (int e = tid; e < 184 * 32; e += 256) {
        int r = e >> 5, d = e & 31;
        int tg = (t0 - 56 + r) & 2047;
        sv1[e] = vb[((long)tg << 9) + d];
    }
    __syncthreads();

    // v2 rows r=0..155 (global t = t0-28+r): v2[t] = sum tL2[k]*v1[t-4k]
    for (int e = tid; e < 156 * 32; e += 256) {
        int r = e >> 5, d = e & 31;
        float a = 0.f;
#pragma unroll
        for (int k = 0; k < 8; k++) a += tL2[k] * sv1[(r + 28 - 4 * k) * 32 + d];
        sv2[e] = a;
    }
    // K = H1(v1) rows 0..127 (independent of sv2 -> no sync needed yet)
    __half* khb = khg + ((long)b << 20) + d0;
    __half* kxb = kxg + ((long)b << 20) + d0;
    for (int e = tid; e < 128 * 32; e += 256) {
        int r = e >> 5, d = e & 31;
        float a = 0.f;
#pragma unroll
        for (int k = 0; k < 8; k++) a += tH1[k] * sv1[(r + 56 - 2 * k) * 32 + d];
        __half hi, xx;
        split_x1(a, hi, xx);
        long off = ((long)(t0 + r) << 9) + d;
        khb[off] = hi;
        kxb[off] = xx;
    }
    __syncthreads();

    // vv = H2(v2) rows 0..127 -> staged (t-major) split halves
    for (int e = tid; e < 128 * 32; e += 256) {
        int r = e >> 5, d = e & 31;
        float a = 0.f;
#pragma unroll
        for (int k = 0; k < 8; k++) a += tH2[k] * sv2[(r + 28 - 4 * k) * 32 + d];
        __half hi, xx;
        split_x1(a, hi, xx);
        vvh[r * 33 + d] = hi;
        vvx[r * 33 + d] = xx;
    }
    __syncthreads();

    // transpose write: vth[bh][dh][t]; thread (dh = tid>>3, tb = tid&7): 16 t each
    const int h = d0 >> 6, dhb = d0 & 63;
    const int bh = b * 8 + h;
    __half* oh = vth + ((long)bh * 64) * Ln + t0;
    __half* ox = vtx + ((long)bh * 64) * Ln + t0;
    const int dh = tid >> 3, tb = (tid & 7) * 16;
    __half* ohr = oh + (long)(dhb + dh) * Ln + tb;
    __half* oxr = ox + (long)(dhb + dh) * Ln + tb;
#pragma unroll
    for (int i = 0; i < 16; i++) {
        ohr[i] = vvh[(tb + i) * 33 + dh];
        oxr[i] = vvx[(tb + i) * 33 + dh];
    }
}

// ---------------------------------------------------------------------------
// 2-MMA scaled-residual flash attention (round 11, exp2 softmax).
// Grid (L/128, B*H), 256 threads = 8 warps; warp owns 16 q-rows; BK=64.
// ---------------------------------------------------------------------------
#define STRW 36
#define TILEW (64 * STRW)
#define BUFW  (4 * TILEW)
#define PHOFF (2 * BUFW)
#define PXOFF (PHOFF + 128 * STRW)
#define ASMEM ((2 * BUFW + 2 * 128 * STRW) * 4)   // 110592

#define QSCALE 0.18033688011112042f   // 0.125 * log2(e) -> exp2 domain

__global__ __launch_bounds__(256, 2) void attn_kernel(
    const float* __restrict__ Qg,
    const __half* __restrict__ Khg, const __half* __restrict__ Kxg,
    const __half* __restrict__ Vhg, const __half* __restrict__ Vxg,
    float* __restrict__ O)
{
    extern __shared__ unsigned sm_u[];
    const uint32_t sb = s2u(sm_u);

    const int tid = threadIdx.x;
    const int lane = tid & 31, warp = tid >> 5;
    const int g = lane >> 2, tg = lane & 3;
    const int bh = blockIdx.y;
    const int b = bh >> 3, h = bh & 7;
    const int q0 = blockIdx.x * 128;

    unsigned qah[4][4], qax[4][4];
    {
        const float* Qp = Qg + ((long)b * Ln + q0 + warp * 16) * Dn + h * 64;
#pragma unroll
        for (int kt = 0; kt < 4; kt++)
#pragma unroll
            for (int part = 0; part < 4; part++) {
                int row = g + (part & 1) * 8;
                int col = kt * 16 + ((part >> 1) << 3) + 2 * tg;
                float2 x = *(const float2*)(Qp + row * Dn + col);
                split_x2(x.x * QSCALE, x.y * QSCALE, qah[kt][part], qax[kt][part]);
            }
    }

    const __half* Kb  = Khg + (long)b * Ln * Dn + h * 64;
    const __half* Kxb = Kxg + (long)b * Ln * Dn + h * 64;
    const __half* Vb  = Vhg + (long)bh * 64 * Ln;
    const __half* Vxb = Vxg + (long)bh * 64 * Ln;

    auto issue_copy = [&](int tile, int bufsel) {
        const int k0 = tile * 64;
        const uint32_t bufbase = sb + (uint32_t)(bufsel * BUFW) * 4u;
#pragma unroll
        for (int j = 0; j < 8; j++) {
            int flat = j * 256 + tid;
            int arr = flat >> 9, rem = flat & 511;
            int row = rem >> 3, c = rem & 7;
            const __half* src;
            uint32_t doff;
            if (arr == 0)      { src = Kb  + (long)(k0 + row) * Dn + c * 8; doff = 0; }
            else if (arr == 1) { src = Kxb + (long)(k0 + row) * Dn + c * 8; doff = TILEW; }
            else if (arr == 2) { src = Vb  + (long)row * Ln + k0 + c * 8;   doff = 2 * TILEW; }
            else               { src = Vxb + (long)row * Ln + k0 + c * 8;   doff = 3 * TILEW; }
            uint32_t daddr = bufbase + (doff + row * STRW + c * 4) * 4u;
            CP_ASYNC16(daddr, src);
        }
        CP_COMMIT();
    };

    float m_[2] = {-1e30f, -1e30f}, l_[2] = {0.f, 0.f};
    float oacc[8][4];
#pragma unroll
    for (int nt = 0; nt < 8; nt++)
#pragma unroll
        for (int j = 0; j < 4; j++) oacc[nt][j] = 0.f;

    unsigned* p0h = sm_u + PHOFF + (warp * 16 + g) * STRW;
    unsigned* p1h = p0h + 8 * STRW;
    unsigned* p0x = sm_u + PXOFF + (warp * 16 + g) * STRW;
    unsigned* p1x = p0x + 8 * STRW;

    issue_copy(0, 0);

    for (int it = 0; it < 32; it++) {
        CP_WAIT0();
        __syncthreads();
        if (it < 31) issue_copy(it + 1, (it + 1) & 1);

        unsigned* buf = sm_u + (it & 1) * BUFW;
        unsigned* sKh = buf;
        unsigned* sKx = buf + TILEW;
        unsigned* sVh = buf + 2 * TILEW;
        unsigned* sVx = buf + 3 * TILEW;

        // ---- S = Q K^T (2-MMA scheme)
        float sc[8][4];
#pragma unroll
        for (int nt = 0; nt < 8; nt++) {
            float ch[4] = {0.f, 0.f, 0.f, 0.f};
            float cx[4] = {0.f, 0.f, 0.f, 0.f};
            const unsigned* krh = sKh + (nt * 8 + g) * STRW;
            const unsigned* krx = sKx + (nt * 8 + g) * STRW;
#pragma unroll
            for (int kt = 0; kt < 4; kt++) {
                mma_f16(ch, qah[kt], krh[kt * 8 + tg], krh[kt * 8 + tg + 4]);
                mma_f16(cx, qax[kt], krx[kt * 8 + tg], krx[kt * 8 + tg + 4]);
            }
#pragma unroll
            for (int j = 0; j < 4; j++) sc[nt][j] = C1 * ch[j] + C2 * cx[j];
        }

        // ---- online softmax (exp2 domain), rows g, g+8
        float rmax[2] = {-1e30f, -1e30f};
#pragma unroll
        for (int nt = 0; nt < 8; nt++) {
            rmax[0] = fmaxf(rmax[0], fmaxf(sc[nt][0], sc[nt][1]));
            rmax[1] = fmaxf(rmax[1], fmaxf(sc[nt][2], sc[nt][3]));
        }
#pragma unroll
        for (int o = 1; o <= 2; o <<= 1) {
            rmax[0] = fmaxf(rmax[0], __shfl_xor_sync(0xffffffffu, rmax[0], o));
            rmax[1] = fmaxf(rmax[1], __shfl_xor_sync(0xffffffffu, rmax[1], o));
        }
        float corr[2];
#pragma unroll
        for (int r = 0; r < 2; r++) {
            float mn = fmaxf(m_[r], rmax[r]);
            corr[r] = ex2f(m_[r] - mn);
            m_[r] = mn;
        }
        float rsum[2] = {0.f, 0.f};
#pragma unroll
        for (int nt = 0; nt < 8; nt++) {
            float p0 = ex2f(sc[nt][0] - m_[0]);
            float p1 = ex2f(sc[nt][1] - m_[0]);
            float p2 = ex2f(sc[nt][2] - m_[1]);
            float p3 = ex2f(sc[nt][3] - m_[1]);
            rsum[0] += p0 + p1; rsum[1] += p2 + p3;
            unsigned h01, x01, h23, x23;
            split_x2(p0, p1, h01, x01);
            split_x2(p2, p3, h23, x23);
            p0h[nt * 4 + tg] = h01; p0x[nt * 4 + tg] = x01;
            p1h[nt * 4 + tg] = h23; p1x[nt * 4 + tg] = x23;
        }
#pragma unroll
        for (int o = 1; o <= 2; o <<= 1) {
            rsum[0] += __shfl_xor_sync(0xffffffffu, rsum[0], o);
            rsum[1] += __shfl_xor_sync(0xffffffffu, rsum[1], o);
        }
        l_[0] = l_[0] * corr[0] + rsum[0];
        l_[1] = l_[1] * corr[1] + rsum[1];
#pragma unroll
        for (int nt = 0; nt < 8; nt++) {
            oacc[nt][0] *= corr[0]; oacc[nt][1] *= corr[0];
            oacc[nt][2] *= corr[1]; oacc[nt][3] *= corr[1];
        }
        __syncwarp();   // P rows are per-warp

        // ---- O += P V (2-MMA scheme; P fragments loaded per kt)
#pragma unroll
        for (int nt = 0; nt < 8; nt++) {
            float ch[4] = {0.f, 0.f, 0.f, 0.f};
            float cx[4] = {0.f, 0.f, 0.f, 0.f};
            const unsigned* vrh = sVh + (nt * 8 + g) * STRW;
            const unsigned* vrx = sVx + (nt * 8 + g) * STRW;
#pragma unroll
            for (int kt = 0; kt < 4; kt++) {
                unsigned pah[4], pax[4];
                pah[0] = p0h[kt * 8 + tg];     pax[0] = p0x[kt * 8 + tg];
                pah[1] = p1h[kt * 8 + tg];     pax[1] = p1x[kt * 8 + tg];
                pah[2] = p0h[kt * 8 + tg + 4]; pax[2] = p0x[kt * 8 + tg + 4];
                pah[3] = p1h[kt * 8 + tg + 4]; pax[3] = p1x[kt * 8 + tg + 4];
                mma_f16(ch, pah, vrh[kt * 8 + tg], vrh[kt * 8 + tg + 4]);
                mma_f16(cx, pax, vrx[kt * 8 + tg], vrx[kt * 8 + tg + 4]);
            }
#pragma unroll
            for (int j = 0; j < 4; j++)
                oacc[nt][j] += C1 * ch[j] + C2 * cx[j];
        }
    }

    // ---- epilogue
    float inv0 = 1.f / l_[0], inv1 = 1.f / l_[1];
    long row0 = (long)b * Ln + q0 + warp * 16 + g;
    long row1 = row0 + 8;
#pragma unroll
    for (int nt = 0; nt < 8; nt++) {
        int col = h * 64 + nt * 8 + 2 * tg;
        float2 v0 = {oacc[nt][0] * inv0, oacc[nt][1] * inv0};
        float2 v1 = {oacc[nt][2] * inv1, oacc[nt][3] * inv1};
        *(float2*)(O + row0 * Dn + col) = v0;
        *(float2*)(O + row1 * Dn + col) = v1;
    }
}

// ---------------------------------------------------------------------------
extern "C" void kernel_launch(void* const* d_in, const int* in_sizes, int n_in,
                              void* d_out, int out_size)
{
    const float* x  = (const float*)d_in[0];
    const float* vf = (const float*)d_in[1];
    const float* wf = (const float*)d_in[2];
    float* out = (float*)d_out;

    float *v1, *q;
    __half *kh, *kx, *vth, *vtx;
    cudaGetSymbolAddress((void**)&v1,  g_v1);
    cudaGetSymbolAddress((void**)&q,   g_q);
    cudaGetSymbolAddress((void**)&kh,  g_kh);
    cudaGetSymbolAddress((void**)&kx,  g_kx);
    cudaGetSymbolAddress((void**)&vth, g_vth);
    cudaGetSymbolAddress((void**)&vtx, g_vtx);

    dim3 cgrid(Ln / 128, Dn / 32, Bn);   // (16, 16, 4) = 1024 blocks

    fconv1_kernel<<<cgrid, 256>>>(x, q, v1, vf, wf);

    cudaFuncSetAttribute(fconv2_kernel,
                         cudaFuncAttributeMaxDynamicSharedMemorySize, K2_SMEM);
    fconv2_kernel<<<cgrid, 256, K2_SMEM>>>(v1, kh, kx, vth, vtx, vf, wf);

    cudaFuncSetAttribute(attn_kernel,
                         cudaFuncAttributeMaxDynamicSharedMemorySize, ASMEM);
    dim3 grid(Ln / 128, Bn * Hn);   // (16, 32)
    attn_kernel<<<grid, 256, ASMEM>>>(q, kh, kx, vth, vtx, out);
}

// round 13
// speedup vs baseline: 1.2209x; 1.2209x over previous
#include <cuda_runtime.h>
#include <cuda_fp16.h>
#include <cstdint>

// ---------------------------------------------------------------------------
// WaveletAttention: 3-level MODWT (db4 dilated circular convs) -> MHA
// B=4, L=2048, D=512, H=8, dh=64
// Round 13: round-11 conv pre-stage (reverted) + 2-MMA scaled-residual
//           attention with REGISTER-RESIDENT P (no P smem) + exp2 softmax
// ---------------------------------------------------------------------------

#define Bn  4
#define Ln  2048
#define Dn  512
#define Hn  8
#define NBD (Bn * Ln * Dn)   // 4,194,304

#define LAM 32.0f
#define C1  0.96875f    // 1 - 1/32
#define C2  0.03125f    // 1/32

__device__ float  g_v0[NBD];
__device__ float  g_v1[NBD];
__device__ float  g_v2[NBD];
__device__ float  g_q [NBD];
__device__ float  g_vv[NBD];
__device__ __half g_kh [NBD];   // K hi, [B][L][D]
__device__ __half g_kx [NBD];   // K X-form
__device__ __half g_vth[NBD];   // V^T hi, [B*H][64][L]
__device__ __half g_vtx[NBD];   // V^T X-form

// ---------------------------------------------------------------------------
__device__ __forceinline__ void split_x2(float x, float y,
                                         unsigned& hi, unsigned& xx) {
    __half hx = __float2half_rn(x);
    __half hy = __float2half_rn(y);
    float fx = __half2float(hx), fy = __half2float(hy);
    __half xxh = __float2half_rn(fx + LAM * (x - fx));
    __half xyh = __float2half_rn(fy + LAM * (y - fy));
    hi = ((unsigned)__half_as_ushort(hy) << 16) | __half_as_ushort(hx);
    xx = ((unsigned)__half_as_ushort(xyh) << 16) | __half_as_ushort(xxh);
}

__device__ __forceinline__ void mma_f16(float* c, const unsigned* a,
                                        unsigned b0, unsigned b1) {
    asm("mma.sync.aligned.m16n8k16.row.col.f32.f16.f16.f32 "
        "{%0,%1,%2,%3}, {%4,%5,%6,%7}, {%8,%9}, {%0,%1,%2,%3};"
        : "+f"(c[0]), "+f"(c[1]), "+f"(c[2]), "+f"(c[3])
        : "r"(a[0]), "r"(a[1]), "r"(a[2]), "r"(a[3]), "r"(b0), "r"(b1));
}

__device__ __forceinline__ float ex2f(float x) {
    float r;
    asm("ex2.approx.ftz.f32 %0, %1;" : "=f"(r) : "f"(x));
    return r;
}

__device__ __forceinline__ uint32_t s2u(const void* p) {
    uint32_t a;
    asm("{ .reg .u64 t; cvta.to.shared.u64 t, %1; cvt.u32.u64 %0, t; }"
        : "=r"(a) : "l"(p));
    return a;
}

#define CP_ASYNC16(daddr, src)                                                 \
    asm volatile("cp.async.cg.shared.global [%0], [%1], 16;"                   \
                 :: "r"(daddr), "l"(src))
#define CP_COMMIT()  asm volatile("cp.async.commit_group;" ::: "memory")
#define CP_WAIT0()   asm volatile("cp.async.wait_group 0;" ::: "memory")

// ---------------------------------------------------------------------------
// 8-tap circular dilated convs (round-11 versions, validated)
// ---------------------------------------------------------------------------
__global__ __launch_bounds__(256) void conv1_kernel(
    const float* __restrict__ in, float* __restrict__ out,
    const float* __restrict__ frow, int dil)
{
    int idx4 = blockIdx.x * 256 + threadIdx.x;
    int d4 = idx4 & 127;
    int t  = (idx4 >> 7) & (Ln - 1);
    int b  = idx4 >> 18;
    const float* inb = in + ((long)b << 20) + (d4 << 2);
    float4 acc = {0.f, 0.f, 0.f, 0.f};
#pragma unroll
    for (int k = 0; k < 8; k++) {
        float tap = __ldg(&frow[(Ln - dil * k) & (Ln - 1)]);
        int src = (t - dil * k) & (Ln - 1);
        float4 v = *(const float4*)(inb + (src << 9));
        acc.x += tap * v.x; acc.y += tap * v.y;
        acc.z += tap * v.z; acc.w += tap * v.w;
    }
    *(float4*)(out + ((long)idx4 << 2)) = acc;
}

__global__ __launch_bounds__(256) void conv2_kernel(
    const float* __restrict__ in,
    float* __restrict__ outA, const float* __restrict__ frowA, int dilA,
    float* __restrict__ outB, const float* __restrict__ frowB, int dilB)
{
    int idx4 = blockIdx.x * 256 + threadIdx.x;
    int d4 = idx4 & 127;
    int t  = (idx4 >> 7) & (Ln - 1);
    int b  = idx4 >> 18;
    const float* inb = in + ((long)b << 20) + (d4 << 2);
    float4 aA = {0.f, 0.f, 0.f, 0.f};
    float4 aB = {0.f, 0.f, 0.f, 0.f};
#pragma unroll
    for (int k = 0; k < 8; k++) {
        float tap = __ldg(&frowA[(Ln - dilA * k) & (Ln - 1)]);
        int src = (t - dilA * k) & (Ln - 1);
        float4 v = *(const float4*)(inb + (src << 9));
        aA.x += tap * v.x; aA.y += tap * v.y;
        aA.z += tap * v.z; aA.w += tap * v.w;
    }
#pragma unroll
    for (int k = 0; k < 8; k++) {
        float tap = __ldg(&frowB[(Ln - dilB * k) & (Ln - 1)]);
        int src = (t - dilB * k) & (Ln - 1);
        float4 v = *(const float4*)(inb + (src << 9));
        aB.x += tap * v.x; aB.y += tap * v.y;
        aB.z += tap * v.z; aB.w += tap * v.w;
    }
    *(float4*)(outA + ((long)idx4 << 2)) = aA;
    *(float4*)(outB + ((long)idx4 << 2)) = aB;
}

__global__ __launch_bounds__(256) void conv2s_kernel(
    const float* __restrict__ in,
    __half* __restrict__ outAh, __half* __restrict__ outAx,
    const float* __restrict__ frowA, int dilA,
    float* __restrict__ outB, const float* __restrict__ frowB, int dilB)
{
    int idx4 = blockIdx.x * 256 + threadIdx.x;
    int d4 = idx4 & 127;
    int t  = (idx4 >> 7) & (Ln - 1);
    int b  = idx4 >> 18;
    const float* inb = in + ((long)b << 20) + (d4 << 2);
    float4 aA = {0.f, 0.f, 0.f, 0.f};
    float4 aB = {0.f, 0.f, 0.f, 0.f};
#pragma unroll
    for (int k = 0; k < 8; k++) {
        float tap = __ldg(&frowA[(Ln - dilA * k) & (Ln - 1)]);
        int src = (t - dilA * k) & (Ln - 1);
        float4 v = *(const float4*)(inb + (src << 9));
        aA.x += tap * v.x; aA.y += tap * v.y;
        aA.z += tap * v.z; aA.w += tap * v.w;
    }
#pragma unroll
    for (int k = 0; k < 8; k++) {
        float tap = __ldg(&frowB[(Ln - dilB * k) & (Ln - 1)]);
        int src = (t - dilB * k) & (Ln - 1);
        float4 v = *(const float4*)(inb + (src << 9));
        aB.x += tap * v.x; aB.y += tap * v.y;
        aB.z += tap * v.z; aB.w += tap * v.w;
    }
    unsigned h01, x01, h23, x23;
    split_x2(aA.x, aA.y, h01, x01);
    split_x2(aA.z, aA.w, h23, x23);
    *(uint2*)(outAh + ((long)idx4 << 2)) = make_uint2(h01, h23);
    *(uint2*)(outAx + ((long)idx4 << 2)) = make_uint2(x01, x23);
    *(float4*)(outB + ((long)idx4 << 2)) = aB;
}

__global__ __launch_bounds__(256) void vtrans_kernel(
    const float* __restrict__ v,
    __half* __restrict__ vth, __half* __restrict__ vtx)
{
    __shared__ float tile[64][65];
    int t0 = blockIdx.x * 64;
    int bh = blockIdx.y;
    int b = bh >> 3, h = bh & 7;
    const float* src = v + ((long)b * Ln + t0) * Dn + h * 64;
#pragma unroll
    for (int it = 0; it < 16; it++) {
        int o = it * 256 + threadIdx.x;
        int r = o >> 6, c = o & 63;
        tile[r][c] = src[(long)r * Dn + c];
    }
    __syncthreads();
    __half* dh_ = vth + (long)bh * 64 * Ln + t0;
    __half* dx_ = vtx + (long)bh * 64 * Ln + t0;
#pragma unroll
    for (int it = 0; it < 16; it++) {
        int o = it * 256 + threadIdx.x;
        int key = o & 63, dh = o >> 6;
        float x = tile[key][dh];
        __half hi = __float2half_rn(x);
        float fh = __half2float(hi);
        __half xx = __float2half_rn(fh + LAM * (x - fh));
        dh_[(long)dh * Ln + key] = hi;
        dx_[(long)dh * Ln + key] = xx;
    }
}

// ---------------------------------------------------------------------------
// 2-MMA scaled-residual flash attention, register-resident P, exp2 softmax.
// Grid (L/128, B*H), 256 threads = 8 warps; warp owns 16 q-rows; BK=64.
// smem: 2 bufs x [Kh|Kx|Vh|Vx][64][36w] = 73,728 B (2 CTA/SM)
// ---------------------------------------------------------------------------
#define STRW 36
#define TILEW (64 * STRW)
#define BUFW  (4 * TILEW)
#define ASMEM (2 * BUFW * 4)   // 73728

#define QSCALE 0.18033688011112042f   // 0.125 * log2(e) -> exp2 domain

__global__ __launch_bounds__(256, 2) void attn_kernel(
    const float* __restrict__ Qg,
    const __half* __restrict__ Khg, const __half* __restrict__ Kxg,
    const __half* __restrict__ Vhg, const __half* __restrict__ Vxg,
    float* __restrict__ O)
{
    extern __shared__ unsigned sm_u[];
    const uint32_t sb = s2u(sm_u);

    const int tid = threadIdx.x;
    const int lane = tid & 31, warp = tid >> 5;
    const int g = lane >> 2, tg = lane & 3;
    const int bh = blockIdx.y;
    const int b = bh >> 3, h = bh & 7;
    const int q0 = blockIdx.x * 128;

    // ---- Q fragments (scaled to exp2 domain, hi/X split)
    unsigned qah[4][4], qax[4][4];
    {
        const float* Qp = Qg + ((long)b * Ln + q0 + warp * 16) * Dn + h * 64;
#pragma unroll
        for (int kt = 0; kt < 4; kt++)
#pragma unroll
            for (int part = 0; part < 4; part++) {
                int row = g + (part & 1) * 8;
                int col = kt * 16 + ((part >> 1) << 3) + 2 * tg;
                float2 x = *(const float2*)(Qp + row * Dn + col);
                split_x2(x.x * QSCALE, x.y * QSCALE, qah[kt][part], qax[kt][part]);
            }
    }

    const __half* Kb  = Khg + (long)b * Ln * Dn + h * 64;
    const __half* Kxb = Kxg + (long)b * Ln * Dn + h * 64;
    const __half* Vb  = Vhg + (long)bh * 64 * Ln;
    const __half* Vxb = Vxg + (long)bh * 64 * Ln;

    auto issue_copy = [&](int tile, int bufsel) {
        const int k0 = tile * 64;
        const uint32_t bufbase = sb + (uint32_t)(bufsel * BUFW) * 4u;
#pragma unroll
        for (int j = 0; j < 8; j++) {
            int flat = j * 256 + tid;
            int arr = flat >> 9, rem = flat & 511;
            int row = rem >> 3, c = rem & 7;
            const __half* src;
            uint32_t doff;
            if (arr == 0)      { src = Kb  + (long)(k0 + row) * Dn + c * 8; doff = 0; }
            else if (arr == 1) { src = Kxb + (long)(k0 + row) * Dn + c * 8; doff = TILEW; }
            else if (arr == 2) { src = Vb  + (long)row * Ln + k0 + c * 8;   doff = 2 * TILEW; }
            else               { src = Vxb + (long)row * Ln + k0 + c * 8;   doff = 3 * TILEW; }
            uint32_t daddr = bufbase + (doff + row * STRW + c * 4) * 4u;
            CP_ASYNC16(daddr, src);
        }
        CP_COMMIT();
    };

    float m_[2] = {-1e30f, -1e30f}, l_[2] = {0.f, 0.f};
    float oacc[8][4];
#pragma unroll
    for (int nt = 0; nt < 8; nt++)
#pragma unroll
        for (int j = 0; j < 4; j++) oacc[nt][j] = 0.f;

    issue_copy(0, 0);

    for (int it = 0; it < 32; it++) {
        CP_WAIT0();
        __syncthreads();
        if (it < 31) issue_copy(it + 1, (it + 1) & 1);

        unsigned* buf = sm_u + (it & 1) * BUFW;
        unsigned* sKh = buf;
        unsigned* sKx = buf + TILEW;
        unsigned* sVh = buf + 2 * TILEW;
        unsigned* sVx = buf + 3 * TILEW;

        // ---- S = Q K^T (2-MMA scheme)
        float sc[8][4];
#pragma unroll
        for (int nt = 0; nt < 8; nt++) {
            float ch[4] = {0.f, 0.f, 0.f, 0.f};
            float cx[4] = {0.f, 0.f, 0.f, 0.f};
            const unsigned* krh = sKh + (nt * 8 + g) * STRW;
            const unsigned* krx = sKx + (nt * 8 + g) * STRW;
#pragma unroll
            for (int kt = 0; kt < 4; kt++) {
                mma_f16(ch, qah[kt], krh[kt * 8 + tg], krh[kt * 8 + tg + 4]);
                mma_f16(cx, qax[kt], krx[kt * 8 + tg], krx[kt * 8 + tg + 4]);
            }
#pragma unroll
            for (int j = 0; j < 4; j++) sc[nt][j] = C1 * ch[j] + C2 * cx[j];
        }

        // ---- online softmax (exp2 domain), rows g, g+8
        float rmax[2] = {-1e30f, -1e30f};
#pragma unroll
        for (int nt = 0; nt < 8; nt++) {
            rmax[0] = fmaxf(rmax[0], fmaxf(sc[nt][0], sc[nt][1]));
            rmax[1] = fmaxf(rmax[1], fmaxf(sc[nt][2], sc[nt][3]));
        }
#pragma unroll
        for (int o = 1; o <= 2; o <<= 1) {
            rmax[0] = fmaxf(rmax[0], __shfl_xor_sync(0xffffffffu, rmax[0], o));
            rmax[1] = fmaxf(rmax[1], __shfl_xor_sync(0xffffffffu, rmax[1], o));
        }
        float corr[2];
#pragma unroll
        for (int r = 0; r < 2; r++) {
            float mn = fmaxf(m_[r], rmax[r]);
            corr[r] = ex2f(m_[r] - mn);
            m_[r] = mn;
        }

        // p-values packed DIRECTLY into A-fragment registers (no smem)
        unsigned ph01[8], ph23[8], px01[8], px23[8];
        float rsum[2] = {0.f, 0.f};
#pragma unroll
        for (int nt = 0; nt < 8; nt++) {
            float p0 = ex2f(sc[nt][0] - m_[0]);
            float p1 = ex2f(sc[nt][1] - m_[0]);
            float p2 = ex2f(sc[nt][2] - m_[1]);
            float p3 = ex2f(sc[nt][3] - m_[1]);
            rsum[0] += p0 + p1; rsum[1] += p2 + p3;
            split_x2(p0, p1, ph01[nt], px01[nt]);
            split_x2(p2, p3, ph23[nt], px23[nt]);
        }
#pragma unroll
        for (int o = 1; o <= 2; o <<= 1) {
            rsum[0] += __shfl_xor_sync(0xffffffffu, rsum[0], o);
            rsum[1] += __shfl_xor_sync(0xffffffffu, rsum[1], o);
        }
        l_[0] = l_[0] * corr[0] + rsum[0];
        l_[1] = l_[1] * corr[1] + rsum[1];
#pragma unroll
        for (int nt = 0; nt < 8; nt++) {
            oacc[nt][0] *= corr[0]; oacc[nt][1] *= corr[0];
            oacc[nt][2] *= corr[1]; oacc[nt][3] *= corr[1];
        }

        // ---- O += P V (2-MMA scheme; P A-fragments straight from registers)
#pragma unroll
        for (int nt = 0; nt < 8; nt++) {
            float ch[4] = {0.f, 0.f, 0.f, 0.f};
            float cx[4] = {0.f, 0.f, 0.f, 0.f};
            const unsigned* vrh = sVh + (nt * 8 + g) * STRW;
            const unsigned* vrx = sVx + (nt * 8 + g) * STRW;
#pragma unroll
            for (int kt = 0; kt < 4; kt++) {
                unsigned pah[4] = {ph01[2 * kt], ph23[2 * kt],
                                   ph01[2 * kt + 1], ph23[2 * kt + 1]};
                unsigned pax[4] = {px01[2 * kt], px23[2 * kt],
                                   px01[2 * kt + 1], px23[2 * kt + 1]};
                mma_f16(ch, pah, vrh[kt * 8 + tg], vrh[kt * 8 + tg + 4]);
                mma_f16(cx, pax, vrx[kt * 8 + tg], vrx[kt * 8 + tg + 4]);
            }
#pragma unroll
            for (int j = 0; j < 4; j++)
                oacc[nt][j] += C1 * ch[j] + C2 * cx[j];
        }
    }

    // ---- epilogue
    float inv0 = 1.f / l_[0], inv1 = 1.f / l_[1];
    long row0 = (long)b * Ln + q0 + warp * 16 + g;
    long row1 = row0 + 8;
#pragma unroll
    for (int nt = 0; nt < 8; nt++) {
        int col = h * 64 + nt * 8 + 2 * tg;
        float2 v0 = {oacc[nt][0] * inv0, oacc[nt][1] * inv0};
        float2 v1 = {oacc[nt][2] * inv1, oacc[nt][3] * inv1};
        *(float2*)(O + row0 * Dn + col) = v0;
        *(float2*)(O + row1 * Dn + col) = v1;
    }
}

// ---------------------------------------------------------------------------
extern "C" void kernel_launch(void* const* d_in, const int* in_sizes, int n_in,
                              void* d_out, int out_size)
{
    const float* x  = (const float*)d_in[0];
    const float* vf = (const float*)d_in[1];
    const float* wf = (const float*)d_in[2];
    float* out = (float*)d_out;

    float *v0, *v1, *v2, *q, *vv;
    __half *kh, *kx, *vth, *vtx;
    cudaGetSymbolAddress((void**)&v0,  g_v0);
    cudaGetSymbolAddress((void**)&v1,  g_v1);
    cudaGetSymbolAddress((void**)&v2,  g_v2);
    cudaGetSymbolAddress((void**)&q,   g_q);
    cudaGetSymbolAddress((void**)&vv,  g_vv);
    cudaGetSymbolAddress((void**)&kh,  g_kh);
    cudaGetSymbolAddress((void**)&kx,  g_kx);
    cudaGetSymbolAddress((void**)&vth, g_vth);
    cudaGetSymbolAddress((void**)&vtx, g_vtx);

    const size_t LL = (size_t)Ln * Ln;
    const int cblocks = (NBD / 4) / 256;

    // v0 = L0(x); {q = H0(v0), v1 = L1(v0)}; {k = H1(v1), v2 = L2(v1)}; vv = H2(v2)
    conv1_kernel<<<cblocks, 256>>>(x, v0, vf, 1);
    conv2_kernel<<<cblocks, 256>>>(v0, q, wf, 1, v1, vf + LL, 2);
    conv2s_kernel<<<cblocks, 256>>>(v1, kh, kx, wf + LL, 2, v2, vf + 2 * LL, 4);
    conv1_kernel<<<cblocks, 256>>>(v2, vv, wf + 2 * LL, 4);
    vtrans_kernel<<<dim3(Ln / 64, Bn * Hn), 256>>>(vv, vth, vtx);

    cudaFuncSetAttribute(attn_kernel,
                         cudaFuncAttributeMaxDynamicSharedMemorySize, ASMEM);
    dim3 grid(Ln / 128, Bn * Hn);   // (16, 32)
    attn_kernel<<<grid, 256, ASMEM>>>(q, kh, kx, vth, vtx, out);
}

// round 14
// speedup vs baseline: 1.2631x; 1.0346x over previous
#include <cuda_runtime.h>
#include <cuda_fp16.h>
#include <cstdint>

// ---------------------------------------------------------------------------
// WaveletAttention: 3-level MODWT (db4 dilated circular convs) -> MHA
// B=4, L=2048, D=512, H=8, dh=64
// Round 14: register-blocked convs (4 t-positions/thread, shared tap loads)
//           + round-13 register-P 2-MMA scaled-residual attention (unchanged)
// ---------------------------------------------------------------------------

#define Bn  4
#define Ln  2048
#define Dn  512
#define Hn  8
#define NBD (Bn * Ln * Dn)   // 4,194,304

#define LAM 32.0f
#define C1  0.96875f    // 1 - 1/32
#define C2  0.03125f    // 1/32

__device__ float  g_v0[NBD];
__device__ float  g_v1[NBD];
__device__ float  g_v2[NBD];
__device__ float  g_q [NBD];
__device__ float  g_vv[NBD];
__device__ __half g_kh [NBD];   // K hi, [B][L][D]
__device__ __half g_kx [NBD];   // K X-form
__device__ __half g_vth[NBD];   // V^T hi, [B*H][64][L]
__device__ __half g_vtx[NBD];   // V^T X-form

// ---------------------------------------------------------------------------
__device__ __forceinline__ void split_x2(float x, float y,
                                         unsigned& hi, unsigned& xx) {
    __half hx = __float2half_rn(x);
    __half hy = __float2half_rn(y);
    float fx = __half2float(hx), fy = __half2float(hy);
    __half xxh = __float2half_rn(fx + LAM * (x - fx));
    __half xyh = __float2half_rn(fy + LAM * (y - fy));
    hi = ((unsigned)__half_as_ushort(hy) << 16) | __half_as_ushort(hx);
    xx = ((unsigned)__half_as_ushort(xyh) << 16) | __half_as_ushort(xxh);
}

__device__ __forceinline__ void mma_f16(float* c, const unsigned* a,
                                        unsigned b0, unsigned b1) {
    asm("mma.sync.aligned.m16n8k16.row.col.f32.f16.f16.f32 "
        "{%0,%1,%2,%3}, {%4,%5,%6,%7}, {%8,%9}, {%0,%1,%2,%3};"
        : "+f"(c[0]), "+f"(c[1]), "+f"(c[2]), "+f"(c[3])
        : "r"(a[0]), "r"(a[1]), "r"(a[2]), "r"(a[3]), "r"(b0), "r"(b1));
}

__device__ __forceinline__ float ex2f(float x) {
    float r;
    asm("ex2.approx.ftz.f32 %0, %1;" : "=f"(r) : "f"(x));
    return r;
}

__device__ __forceinline__ uint32_t s2u(const void* p) {
    uint32_t a;
    asm("{ .reg .u64 t; cvta.to.shared.u64 t, %1; cvt.u32.u64 %0, t; }"
        : "=r"(a) : "l"(p));
    return a;
}

#define CP_ASYNC16(daddr, src)                                                 \
    asm volatile("cp.async.cg.shared.global [%0], [%1], 16;"                   \
                 :: "r"(daddr), "l"(src))
#define CP_COMMIT()  asm volatile("cp.async.commit_group;" ::: "memory")
#define CP_WAIT0()   asm volatile("cp.async.wait_group 0;" ::: "memory")

#define FMA4(acc, t, v)                                                        \
    do { acc.x += (t) * (v).x; acc.y += (t) * (v).y;                           \
         acc.z += (t) * (v).z; acc.w += (t) * (v).w; } while (0)

// ---------------------------------------------------------------------------
// Register-blocked convs: thread computes 4 t-positions spaced by dil.
// t = base + dil*j, base = (u & (dil-1)) + ((u >> ldil) << (ldil+2))
// ---------------------------------------------------------------------------
__global__ __launch_bounds__(256) void conv1_kernel(
    const float* __restrict__ in, float* __restrict__ out,
    const float* __restrict__ frow, int dil, int ldil)
{
    int idx = blockIdx.x * 256 + threadIdx.x;   // over NBD/16 = 262144
    int d4 = idx & 127;
    int u  = (idx >> 7) & 511;
    int b  = idx >> 16;
    int base = (u & (dil - 1)) + ((u >> ldil) << (ldil + 2));

    const float* inb = in + ((long)b << 20) + (d4 << 2);
    float tap[8];
#pragma unroll
    for (int k = 0; k < 8; k++)
        tap[k] = __ldg(&frow[(Ln - dil * k) & (Ln - 1)]);

    float4 xv[11];                               // offsets e-7 in [-7, 3]
#pragma unroll
    for (int e = 0; e < 11; e++) {
        int src = (base + dil * (e - 7)) & (Ln - 1);
        xv[e] = *(const float4*)(inb + (src << 9));
    }

    float* ob = out + ((long)b << 20) + (d4 << 2);
#pragma unroll
    for (int j = 0; j < 4; j++) {
        float4 acc = {0.f, 0.f, 0.f, 0.f};
#pragma unroll
        for (int k = 0; k < 8; k++) FMA4(acc, tap[k], xv[7 + j - k]);
        int t = base + dil * j;
        *(float4*)(ob + ((long)t << 9)) = acc;
    }
}

// two filters: A at dilation dil, B at dilation 2*dil; grouped at stride dil
__global__ __launch_bounds__(256) void conv2_kernel(
    const float* __restrict__ in,
    float* __restrict__ outA, const float* __restrict__ frowA,
    float* __restrict__ outB, const float* __restrict__ frowB,
    int dil, int ldil)
{
    int idx = blockIdx.x * 256 + threadIdx.x;
    int d4 = idx & 127;
    int u  = (idx >> 7) & 511;
    int b  = idx >> 16;
    int base = (u & (dil - 1)) + ((u >> ldil) << (ldil + 2));

    const float* inb = in + ((long)b << 20) + (d4 << 2);
    float tA[8], tB[8];
#pragma unroll
    for (int k = 0; k < 8; k++) {
        tA[k] = __ldg(&frowA[(Ln - dil * k) & (Ln - 1)]);
        tB[k] = __ldg(&frowB[(Ln - 2 * dil * k) & (Ln - 1)]);
    }

    float4 xv[18];                               // offsets e-14 in [-14, 3]
#pragma unroll
    for (int e = 0; e < 18; e++) {
        int src = (base + dil * (e - 14)) & (Ln - 1);
        xv[e] = *(const float4*)(inb + (src << 9));
    }

    float* oa = outA + ((long)b << 20) + (d4 << 2);
    float* ob = outB + ((long)b << 20) + (d4 << 2);
#pragma unroll
    for (int j = 0; j < 4; j++) {
        float4 aA = {0.f, 0.f, 0.f, 0.f};
        float4 aB = {0.f, 0.f, 0.f, 0.f};
#pragma unroll
        for (int k = 0; k < 8; k++) {
            FMA4(aA, tA[k], xv[14 + j - k]);
            FMA4(aB, tB[k], xv[14 + j - 2 * k]);
        }
        long off = ((long)(base + dil * j) << 9);
        *(float4*)(oa + off) = aA;
        *(float4*)(ob + off) = aB;
    }
}

// A (dil) -> fp16 hi/X split, B (2*dil) -> f32. Used for K (dil=2) + v2.
__global__ __launch_bounds__(256) void conv2s_kernel(
    const float* __restrict__ in,
    __half* __restrict__ outAh, __half* __restrict__ outAx,
    const float* __restrict__ frowA,
    float* __restrict__ outB, const float* __restrict__ frowB,
    int dil, int ldil)
{
    int idx = blockIdx.x * 256 + threadIdx.x;
    int d4 = idx & 127;
    int u  = (idx >> 7) & 511;
    int b  = idx >> 16;
    int base = (u & (dil - 1)) + ((u >> ldil) << (ldil + 2));

    const float* inb = in + ((long)b << 20) + (d4 << 2);
    float tA[8], tB[8];
#pragma unroll
    for (int k = 0; k < 8; k++) {
        tA[k] = __ldg(&frowA[(Ln - dil * k) & (Ln - 1)]);
        tB[k] = __ldg(&frowB[(Ln - 2 * dil * k) & (Ln - 1)]);
    }

    float4 xv[18];
#pragma unroll
    for (int e = 0; e < 18; e++) {
        int src = (base + dil * (e - 14)) & (Ln - 1);
        xv[e] = *(const float4*)(inb + (src << 9));
    }

    __half* oah = outAh + ((long)b << 20) + (d4 << 2);
    __half* oax = outAx + ((long)b << 20) + (d4 << 2);
    float*  ob  = outB  + ((long)b << 20) + (d4 << 2);
#pragma unroll
    for (int j = 0; j < 4; j++) {
        float4 aA = {0.f, 0.f, 0.f, 0.f};
        float4 aB = {0.f, 0.f, 0.f, 0.f};
#pragma unroll
        for (int k = 0; k < 8; k++) {
            FMA4(aA, tA[k], xv[14 + j - k]);
            FMA4(aB, tB[k], xv[14 + j - 2 * k]);
        }
        long off = ((long)(base + dil * j) << 9);
        unsigned h01, x01, h23, x23;
        split_x2(aA.x, aA.y, h01, x01);
        split_x2(aA.z, aA.w, h23, x23);
        *(uint2*)(oah + off) = make_uint2(h01, h23);
        *(uint2*)(oax + off) = make_uint2(x01, x23);
        *(float4*)(ob + off) = aB;
    }
}

__global__ __launch_bounds__(256) void vtrans_kernel(
    const float* __restrict__ v,
    __half* __restrict__ vth, __half* __restrict__ vtx)
{
    __shared__ float tile[64][65];
    int t0 = blockIdx.x * 64;
    int bh = blockIdx.y;
    int b = bh >> 3, h = bh & 7;
    const float* src = v + ((long)b * Ln + t0) * Dn + h * 64;
#pragma unroll
    for (int it = 0; it < 16; it++) {
        int o = it * 256 + threadIdx.x;
        int r = o >> 6, c = o & 63;
        tile[r][c] = src[(long)r * Dn + c];
    }
    __syncthreads();
    __half* dh_ = vth + (long)bh * 64 * Ln + t0;
    __half* dx_ = vtx + (long)bh * 64 * Ln + t0;
#pragma unroll
    for (int it = 0; it < 16; it++) {
        int o = it * 256 + threadIdx.x;
        int key = o & 63, dh = o >> 6;
        float x = tile[key][dh];
        __half hi = __float2half_rn(x);
        float fh = __half2float(hi);
        __half xx = __float2half_rn(fh + LAM * (x - fh));
        dh_[(long)dh * Ln + key] = hi;
        dx_[(long)dh * Ln + key] = xx;
    }
}

// ---------------------------------------------------------------------------
// 2-MMA scaled-residual flash attention, register-resident P, exp2 softmax.
// (round-13 kernel, unchanged)
// ---------------------------------------------------------------------------
#define STRW 36
#define TILEW (64 * STRW)
#define BUFW  (4 * TILEW)
#define ASMEM (2 * BUFW * 4)   // 73728

#define QSCALE 0.18033688011112042f   // 0.125 * log2(e) -> exp2 domain

__global__ __launch_bounds__(256, 2) void attn_kernel(
    const float* __restrict__ Qg,
    const __half* __restrict__ Khg, const __half* __restrict__ Kxg,
    const __half* __restrict__ Vhg, const __half* __restrict__ Vxg,
    float* __restrict__ O)
{
    extern __shared__ unsigned sm_u[];
    const uint32_t sb = s2u(sm_u);

    const int tid = threadIdx.x;
    const int lane = tid & 31, warp = tid >> 5;
    const int g = lane >> 2, tg = lane & 3;
    const int bh = blockIdx.y;
    const int b = bh >> 3, h = bh & 7;
    const int q0 = blockIdx.x * 128;

    unsigned qah[4][4], qax[4][4];
    {
        const float* Qp = Qg + ((long)b * Ln + q0 + warp * 16) * Dn + h * 64;
#pragma unroll
        for (int kt = 0; kt < 4; kt++)
#pragma unroll
            for (int part = 0; part < 4; part++) {
                int row = g + (part & 1) * 8;
                int col = kt * 16 + ((part >> 1) << 3) + 2 * tg;
                float2 x = *(const float2*)(Qp + row * Dn + col);
                split_x2(x.x * QSCALE, x.y * QSCALE, qah[kt][part], qax[kt][part]);
            }
    }

    const __half* Kb  = Khg + (long)b * Ln * Dn + h * 64;
    const __half* Kxb = Kxg + (long)b * Ln * Dn + h * 64;
    const __half* Vb  = Vhg + (long)bh * 64 * Ln;
    const __half* Vxb = Vxg + (long)bh * 64 * Ln;

    auto issue_copy = [&](int tile, int bufsel) {
        const int k0 = tile * 64;
        const uint32_t bufbase = sb + (uint32_t)(bufsel * BUFW) * 4u;
#pragma unroll
        for (int j = 0; j < 8; j++) {
            int flat = j * 256 + tid;
            int arr = flat >> 9, rem = flat & 511;
            int row = rem >> 3, c = rem & 7;
            const __half* src;
            uint32_t doff;
            if (arr == 0)      { src = Kb  + (long)(k0 + row) * Dn + c * 8; doff = 0; }
            else if (arr == 1) { src = Kxb + (long)(k0 + row) * Dn + c * 8; doff = TILEW; }
            else if (arr == 2) { src = Vb  + (long)row * Ln + k0 + c * 8;   doff = 2 * TILEW; }
            else               { src = Vxb + (long)row * Ln + k0 + c * 8;   doff = 3 * TILEW; }
            uint32_t daddr = bufbase + (doff + row * STRW + c * 4) * 4u;
            CP_ASYNC16(daddr, src);
        }
        CP_COMMIT();
    };

    float m_[2] = {-1e30f, -1e30f}, l_[2] = {0.f, 0.f};
    float oacc[8][4];
#pragma unroll
    for (int nt = 0; nt < 8; nt++)
#pragma unroll
        for (int j = 0; j < 4; j++) oacc[nt][j] = 0.f;

    issue_copy(0, 0);

    for (int it = 0; it < 32; it++) {
        CP_WAIT0();
        __syncthreads();
        if (it < 31) issue_copy(it + 1, (it + 1) & 1);

        unsigned* buf = sm_u + (it & 1) * BUFW;
        unsigned* sKh = buf;
        unsigned* sKx = buf + TILEW;
        unsigned* sVh = buf + 2 * TILEW;
        unsigned* sVx = buf + 3 * TILEW;

        // ---- S = Q K^T (2-MMA scheme)
        float sc[8][4];
#pragma unroll
        for (int nt = 0; nt < 8; nt++) {
            float ch[4] = {0.f, 0.f, 0.f, 0.f};
            float cx[4] = {0.f, 0.f, 0.f, 0.f};
            const unsigned* krh = sKh + (nt * 8 + g) * STRW;
            const unsigned* krx = sKx + (nt * 8 + g) * STRW;
#pragma unroll
            for (int kt = 0; kt < 4; kt++) {
                mma_f16(ch, qah[kt], krh[kt * 8 + tg], krh[kt * 8 + tg + 4]);
                mma_f16(cx, qax[kt], krx[kt * 8 + tg], krx[kt * 8 + tg + 4]);
            }
#pragma unroll
            for (int j = 0; j < 4; j++) sc[nt][j] = C1 * ch[j] + C2 * cx[j];
        }

        // ---- online softmax (exp2 domain), rows g, g+8
        float rmax[2] = {-1e30f, -1e30f};
#pragma unroll
        for (int nt = 0; nt < 8; nt++) {
            rmax[0] = fmaxf(rmax[0], fmaxf(sc[nt][0], sc[nt][1]));
            rmax[1] = fmaxf(rmax[1], fmaxf(sc[nt][2], sc[nt][3]));
        }
#pragma unroll
        for (int o = 1; o <= 2; o <<= 1) {
            rmax[0] = fmaxf(rmax[0], __shfl_xor_sync(0xffffffffu, rmax[0], o));
            rmax[1] = fmaxf(rmax[1], __shfl_xor_sync(0xffffffffu, rmax[1], o));
        }
        float corr[2];
#pragma unroll
        for (int r = 0; r < 2; r++) {
            float mn = fmaxf(m_[r], rmax[r]);
            corr[r] = ex2f(m_[r] - mn);
            m_[r] = mn;
        }

        unsigned ph01[8], ph23[8], px01[8], px23[8];
        float rsum[2] = {0.f, 0.f};
#pragma unroll
        for (int nt = 0; nt < 8; nt++) {
            float p0 = ex2f(sc[nt][0] - m_[0]);
            float p1 = ex2f(sc[nt][1] - m_[0]);
            float p2 = ex2f(sc[nt][2] - m_[1]);
            float p3 = ex2f(sc[nt][3] - m_[1]);
            rsum[0] += p0 + p1; rsum[1] += p2 + p3;
            split_x2(p0, p1, ph01[nt], px01[nt]);
            split_x2(p2, p3, ph23[nt], px23[nt]);
        }
#pragma unroll
        for (int o = 1; o <= 2; o <<= 1) {
            rsum[0] += __shfl_xor_sync(0xffffffffu, rsum[0], o);
            rsum[1] += __shfl_xor_sync(0xffffffffu, rsum[1], o);
        }
        l_[0] = l_[0] * corr[0] + rsum[0];
        l_[1] = l_[1] * corr[1] + rsum[1];
#pragma unroll
        for (int nt = 0; nt < 8; nt++) {
            oacc[nt][0] *= corr[0]; oacc[nt][1] *= corr[0];
            oacc[nt][2] *= corr[1]; oacc[nt][3] *= corr[1];
        }

        // ---- O += P V (P A-fragments straight from registers)
#pragma unroll
        for (int nt = 0; nt < 8; nt++) {
            float ch[4] = {0.f, 0.f, 0.f, 0.f};
            float cx[4] = {0.f, 0.f, 0.f, 0.f};
            const unsigned* vrh = sVh + (nt * 8 + g) * STRW;
            const unsigned* vrx = sVx + (nt * 8 + g) * STRW;
#pragma unroll
            for (int kt = 0; kt < 4; kt++) {
                unsigned pah[4] = {ph01[2 * kt], ph23[2 * kt],
                                   ph01[2 * kt + 1], ph23[2 * kt + 1]};
                unsigned pax[4] = {px01[2 * kt], px23[2 * kt],
                                   px01[2 * kt + 1], px23[2 * kt + 1]};
                mma_f16(ch, pah, vrh[kt * 8 + tg], vrh[kt * 8 + tg + 4]);
                mma_f16(cx, pax, vrx[kt * 8 + tg], vrx[kt * 8 + tg + 4]);
            }
#pragma unroll
            for (int j = 0; j < 4; j++)
                oacc[nt][j] += C1 * ch[j] + C2 * cx[j];
        }
    }

    // ---- epilogue
    float inv0 = 1.f / l_[0], inv1 = 1.f / l_[1];
    long row0 = (long)b * Ln + q0 + warp * 16 + g;
    long row1 = row0 + 8;
#pragma unroll
    for (int nt = 0; nt < 8; nt++) {
        int col = h * 64 + nt * 8 + 2 * tg;
        float2 v0 = {oacc[nt][0] * inv0, oacc[nt][1] * inv0};
        float2 v1 = {oacc[nt][2] * inv1, oacc[nt][3] * inv1};
        *(float2*)(O + row0 * Dn + col) = v0;
        *(float2*)(O + row1 * Dn + col) = v1;
    }
}

// ---------------------------------------------------------------------------
extern "C" void kernel_launch(void* const* d_in, const int* in_sizes, int n_in,
                              void* d_out, int out_size)
{
    const float* x  = (const float*)d_in[0];
    const float* vf = (const float*)d_in[1];
    const float* wf = (const float*)d_in[2];
    float* out = (float*)d_out;

    float *v0, *v1, *v2, *q, *vv;
    __half *kh, *kx, *vth, *vtx;
    cudaGetSymbolAddress((void**)&v0,  g_v0);
    cudaGetSymbolAddress((void**)&v1,  g_v1);
    cudaGetSymbolAddress((void**)&v2,  g_v2);
    cudaGetSymbolAddress((void**)&q,   g_q);
    cudaGetSymbolAddress((void**)&vv,  g_vv);
    cudaGetSymbolAddress((void**)&kh,  g_kh);
    cudaGetSymbolAddress((void**)&kx,  g_kx);
    cudaGetSymbolAddress((void**)&vth, g_vth);
    cudaGetSymbolAddress((void**)&vtx, g_vtx);

    const size_t LL = (size_t)Ln * Ln;
    const int cblocks = (NBD / 16) / 256;   // 1024

    // v0 = L0(x); {q = H0(v0), v1 = L1(v0)}; {k = H1(v1), v2 = L2(v1)}; vv = H2(v2)
    conv1_kernel<<<cblocks, 256>>>(x, v0, vf, 1, 0);
    conv2_kernel<<<cblocks, 256>>>(v0, q, wf, v1, vf + LL, 1, 0);
    conv2s_kernel<<<cblocks, 256>>>(v1, kh, kx, wf + LL, v2, vf + 2 * LL, 2, 1);
    conv1_kernel<<<cblocks, 256>>>(v2, vv, wf + 2 * LL, 4, 2);
    vtrans_kernel<<<dim3(Ln / 64, Bn * Hn), 256>>>(vv, vth, vtx);

    cudaFuncSetAttribute(attn_kernel,
                         cudaFuncAttributeMaxDynamicSharedMemorySize, ASMEM);
    dim3 grid(Ln / 128, Bn * Hn);   // (16, 32)
    attn_kernel<<<grid, 256, ASMEM>>>(q, kh, kx, vth, vtx, out);
}